// round 16
// baseline (speedup 1.0000x reference)
#include <cuda_runtime.h>
#include <cuda_bf16.h>
#include <cuda_fp16.h>
#include <math.h>
#include <stdint.h>

#define NMAX 50000
#define EMAX 800000
#define DH   128
#define MTILE 128
#define PADK 136      // bf16 elements per padded SMEM row (272 B)

// ---------------------------------------------------------------------------
// Scratch (__device__ globals; allocation-free rule)
// ---------------------------------------------------------------------------
__device__ float  g_agg[(size_t)NMAX * DH];
__device__ __half g_S  [(size_t)NMAX * 512];   // fp16 [Am|Cv|Bm|Dv] per node
__device__ __half g_xf [(size_t)NMAX * DH];    // fp16 x   (gather input, layer 1)
__device__ __half g_h1f[(size_t)NMAX * DH];    // fp16 h1  (gather input, layer 2)

__device__ __nv_bfloat16 g_h1h [(size_t)NMAX * DH];
__device__ __nv_bfloat16 g_h1l [(size_t)NMAX * DH];
__device__ __nv_bfloat16 g_h2h [(size_t)NMAX * DH];
__device__ __nv_bfloat16 g_h2l [(size_t)NMAX * DH];
__device__ __nv_bfloat16 g_Wh[8 * 128 * 128];
__device__ __nv_bfloat16 g_Wl[8 * 128 * 128];

// CSR scratch
__device__ int g_deg   [NMAX + 64];
__device__ int g_off   [NMAX + 64];
__device__ int g_cursor[NMAX + 64];
__device__ int g_csr   [EMAX];
__device__ int g_csre  [EMAX];     // edge id per CSR slot
__device__ int g_blk   [128];      // per-block sums for the scan

// ---------------------------------------------------------------------------
// helpers
// ---------------------------------------------------------------------------
__device__ __forceinline__ uint32_t smem_to_u32(const void* p) {
    uint32_t a;
    asm("{ .reg .u64 t; cvta.to.shared.u64 t, %1; cvt.u32.u64 %0, t; }"
        : "=r"(a) : "l"(p));
    return a;
}
__device__ __forceinline__ void ldsm_x4(uint32_t* r, uint32_t addr) {
    asm volatile("ldmatrix.sync.aligned.m8n8.x4.shared.b16 {%0,%1,%2,%3}, [%4];"
                 : "=r"(r[0]), "=r"(r[1]), "=r"(r[2]), "=r"(r[3]) : "r"(addr));
}
__device__ __forceinline__ void mma16816(float* c, const uint32_t* a, const uint32_t* b) {
    asm volatile(
        "mma.sync.aligned.m16n8k16.row.col.f32.bf16.bf16.f32 "
        "{%0,%1,%2,%3}, {%4,%5,%6,%7}, {%8,%9}, {%0,%1,%2,%3};"
        : "+f"(c[0]), "+f"(c[1]), "+f"(c[2]), "+f"(c[3])
        : "r"(a[0]), "r"(a[1]), "r"(a[2]), "r"(a[3]), "r"(b[0]), "r"(b[1]));
}
__device__ __forceinline__ void split2(float v0, float v1, uint32_t& hi, uint32_t& lo)
{
    __nv_bfloat162 h;
    h.x = __float2bfloat16(v0);
    h.y = __float2bfloat16(v1);
    __nv_bfloat162 l;
    l.x = __float2bfloat16(v0 - __bfloat162float(h.x));
    l.y = __float2bfloat16(v1 - __bfloat162float(h.y));
    hi = *reinterpret_cast<uint32_t*>(&h);
    lo = *reinterpret_cast<uint32_t*>(&l);
}

// ---------------------------------------------------------------------------
// fp32 -> fp16 convert (vectorized x4)
// ---------------------------------------------------------------------------
__global__ void k_half(const float* __restrict__ src, __half* __restrict__ dst, int n4)
{
    int i = blockIdx.x * blockDim.x + threadIdx.x;
    if (i >= n4) return;
    float4 v = reinterpret_cast<const float4*>(src)[i];
    __half2 p0 = __floats2half2_rn(v.x, v.y);
    __half2 p1 = __floats2half2_rn(v.z, v.w);
    reinterpret_cast<__half2*>(dst)[i * 2]     = p0;
    reinterpret_cast<__half2*>(dst)[i * 2 + 1] = p1;
}

// ---------------------------------------------------------------------------
// CSR build
// ---------------------------------------------------------------------------
__global__ void k_zeroi(int* __restrict__ p, int n)
{
    int i = blockIdx.x * blockDim.x + threadIdx.x;
    if (i < n) p[i] = 0;
}

__global__ void k_hist(const int* __restrict__ ei, int E, int* __restrict__ deg)
{
    int e = blockIdx.x * blockDim.x + threadIdx.x;
    if (e < E) atomicAdd(&deg[ei[(size_t)E + e]], 1);
}

__global__ void k_scan1(const int* __restrict__ deg, int* __restrict__ off,
                        int* __restrict__ blk, int N)
{
    __shared__ int sWarp[32];
    const int t    = threadIdx.x;
    const int lane = t & 31;
    const int w    = t >> 5;
    int i = blockIdx.x * 1024 + t;
    int v = (i < N) ? deg[i] : 0;

    int x = v;
#pragma unroll
    for (int d = 1; d < 32; d <<= 1) {
        int y = __shfl_up_sync(0xFFFFFFFFu, x, d);
        if (lane >= d) x += y;
    }
    if (lane == 31) sWarp[w] = x;
    __syncthreads();
    if (w == 0) {
        int s = sWarp[lane];
#pragma unroll
        for (int d = 1; d < 32; d <<= 1) {
            int y = __shfl_up_sync(0xFFFFFFFFu, s, d);
            if (lane >= d) s += y;
        }
        sWarp[lane] = s;
    }
    __syncthreads();
    int warpBase = (w > 0) ? sWarp[w - 1] : 0;
    if (i < N) off[i] = warpBase + (x - v);
    if (t == 1023) blk[blockIdx.x] = sWarp[31];
}

__global__ void k_scan2(int* __restrict__ blk, int* __restrict__ off, int nB, int N)
{
    const int t = threadIdx.x;   // 64 threads
    int v = (t < nB) ? blk[t] : 0;
    int x = v;
#pragma unroll
    for (int d = 1; d < 32; d <<= 1) {
        int y = __shfl_up_sync(0xFFFFFFFFu, x, d);
        if ((t & 31) >= d) x += y;
    }
    __shared__ int sw[2];
    if ((t & 31) == 31) sw[t >> 5] = x;
    __syncthreads();
    int base = (t >= 32) ? sw[0] : 0;
    int excl = base + x - v;
    if (t < nB) blk[t] = excl;
    if (t == 63) off[N] = base + ((nB > 32) ? sw[1] : ((nB > 0) ? sw[0] : 0));
}

__global__ void k_scan3(int* __restrict__ off, int* __restrict__ cursor,
                        const int* __restrict__ blk, int N)
{
    int i = blockIdx.x * 1024 + threadIdx.x;
    if (i < N) {
        int o = off[i] + blk[blockIdx.x];
        off[i] = o;
        cursor[i] = o;
    }
}

__global__ void k_fill(const int* __restrict__ ei, int E,
                       int* __restrict__ cursor,
                       int* __restrict__ csr, int* __restrict__ csre)
{
    int e = blockIdx.x * blockDim.x + threadIdx.x;
    if (e >= E) return;
    int s = ei[e];
    int d = ei[(size_t)E + e];
    int pos = atomicAdd(&cursor[d], 1);
    csr[pos]  = s;
    csre[pos] = e;
}

// ---------------------------------------------------------------------------
// gather-reduce (fp16 input): agg[n] = sum_{e: dst=n} feat[src_e]; warp/node
// ---------------------------------------------------------------------------
__global__ void k_gather(const __half* __restrict__ feat,
                         const int* __restrict__ csr, const int* __restrict__ off,
                         float* __restrict__ agg, int N)
{
    int g = blockIdx.x * blockDim.x + threadIdx.x;
    int n = g >> 5, lane = g & 31;
    if (n >= N) return;
    int s0 = off[n], s1 = off[n + 1];
    float4 acc = make_float4(0.f, 0.f, 0.f, 0.f);
    for (int base = s0; base < s1; base += 32) {
        int cnt = min(32, s1 - base);
        int idx = (base + lane < s1) ? csr[base + lane] : 0;
#pragma unroll 4
        for (int j = 0; j < cnt; ++j) {
            int s = __shfl_sync(0xFFFFFFFFu, idx, j);
            uint2 raw = *reinterpret_cast<const uint2*>(&feat[(size_t)s * DH + lane * 4]);
            __half2 h0 = *reinterpret_cast<__half2*>(&raw.x);
            __half2 h1 = *reinterpret_cast<__half2*>(&raw.y);
            float2 f0 = __half22float2(h0);
            float2 f1 = __half22float2(h1);
            acc.x += f0.x; acc.y += f0.y; acc.z += f1.x; acc.w += f1.y;
        }
    }
    *reinterpret_cast<float4*>(&agg[(size_t)n * DH + lane * 4]) = acc;
}

// ---------------------------------------------------------------------------
// weight prep: transpose [k][n] -> [n][k], split to bf16 hi/lo. 8 units.
// ---------------------------------------------------------------------------
struct WSrc { const float* p[8]; };

__global__ void k_wprep(WSrc w,
                        __nv_bfloat16* __restrict__ oh,
                        __nv_bfloat16* __restrict__ ol)
{
    int u = blockIdx.y;
    int i = blockIdx.x * 256 + threadIdx.x;
    int n = i >> 7, k = i & 127;
    float v = w.p[u][(size_t)k * DH + n];
    __nv_bfloat16 h = __float2bfloat16(v);
    oh[(size_t)u * 16384 + i] = h;
    ol[(size_t)u * 16384 + i] = __float2bfloat16(v - __bfloat162float(h));
}

// ---------------------------------------------------------------------------
// mma.sync bf16 GEMM, error-compensated split (hi*hi + hi*lo + lo*hi).
// 512 threads, 16 warps, warp tile 16x64. Paired-ni ldmatrix.x4 for B.
// Outputs: optional fp16 C (cef), optional bf16 hi/lo split (chi/clo).
// ---------------------------------------------------------------------------
__global__ __launch_bounds__(512)
void k_gemm_mma(const float* __restrict__ a0f,
                const __nv_bfloat16* __restrict__ a0h, const __nv_bfloat16* __restrict__ a0l,
                const __nv_bfloat16* __restrict__ w0h, const __nv_bfloat16* __restrict__ w0l,
                const float* __restrict__ a1f,
                const __nv_bfloat16* __restrict__ a1h, const __nv_bfloat16* __restrict__ a1l,
                const __nv_bfloat16* __restrict__ w1h, const __nv_bfloat16* __restrict__ w1l,
                const float* __restrict__ bias,
                __half* __restrict__ cef,
                __nv_bfloat16* __restrict__ chi, __nv_bfloat16* __restrict__ clo,
                int M, int relu)
{
    extern __shared__ __nv_bfloat16 sm[];
    __nv_bfloat16* sAh = sm;
    __nv_bfloat16* sAl = sAh + 128 * PADK;
    __nv_bfloat16* sBh = sAl + 128 * PADK;
    __nv_bfloat16* sBl = sBh + 128 * PADK;

    const int tid  = threadIdx.x;
    const int wid  = tid >> 5;
    const int lane = tid & 31;
    const int m0   = blockIdx.x * MTILE;
    const int wm   = (wid >> 1) * 16;
    const int wn   = (wid & 1) * 64;

    const uint32_t uAh = smem_to_u32(sAh);
    const uint32_t uAl = smem_to_u32(sAl);
    const uint32_t uBh = smem_to_u32(sBh);
    const uint32_t uBl = smem_to_u32(sBl);

    float acc[8][4];
#pragma unroll
    for (int ni = 0; ni < 8; ++ni)
#pragma unroll
        for (int q = 0; q < 4; ++q) acc[ni][q] = 0.f;

#pragma unroll 1
    for (int phase = 0; phase < 2; ++phase) {
        const float*         Af = phase ? a1f : a0f;
        const __nv_bfloat16* Ah = phase ? a1h : a0h;
        const __nv_bfloat16* Al = phase ? a1l : a0l;
        const __nv_bfloat16* Wh = phase ? w1h : w0h;
        const __nv_bfloat16* Wl = phase ? w1l : w0l;
        if (Af == nullptr && Ah == nullptr) break;

        __syncthreads();
#pragma unroll
        for (int it = 0; it < 4; ++it) {
            int idx = tid + it * 512;          // 0..2047 uint4 slots
            int row = idx >> 4;
            int c8  = (idx & 15) << 3;
            size_t soff = (size_t)row * PADK + c8;
            uint4 vh = make_uint4(0, 0, 0, 0), vl = vh;
            if (m0 + row < M) {
                if (Af) {
                    const float* ap = Af + (size_t)(m0 + row) * DH + c8;
                    float4 f0 = *reinterpret_cast<const float4*>(ap);
                    float4 f1 = *reinterpret_cast<const float4*>(ap + 4);
                    split2(f0.x, f0.y, vh.x, vl.x);
                    split2(f0.z, f0.w, vh.y, vl.y);
                    split2(f1.x, f1.y, vh.z, vl.z);
                    split2(f1.z, f1.w, vh.w, vl.w);
                } else {
                    vh = *reinterpret_cast<const uint4*>(Ah + (size_t)(m0 + row) * DH + c8);
                    vl = *reinterpret_cast<const uint4*>(Al + (size_t)(m0 + row) * DH + c8);
                }
            }
            *reinterpret_cast<uint4*>(sAh + soff) = vh;
            *reinterpret_cast<uint4*>(sAl + soff) = vl;
            *reinterpret_cast<uint4*>(sBh + soff) =
                *reinterpret_cast<const uint4*>(Wh + (size_t)row * DH + c8);
            *reinterpret_cast<uint4*>(sBl + soff) =
                *reinterpret_cast<const uint4*>(Wl + (size_t)row * DH + c8);
        }
        __syncthreads();

#pragma unroll 1
        for (int kc = 0; kc < 8; ++kc) {
            int k0 = kc * 16;
            uint32_t a_off = (uint32_t)(((wm + (lane & 15)) * PADK + k0 + (lane >> 4) * 8) * 2);
            uint32_t ah[4], al[4];
            ldsm_x4(ah, uAh + a_off);
            ldsm_x4(al, uAl + a_off);
            uint32_t b4_off = (uint32_t)(((wn + (lane & 7) + ((lane >> 4) << 3)) * PADK
                                          + k0 + ((lane >> 3) & 1) * 8) * 2);
            uint32_t bh[16], bl[16];
#pragma unroll
            for (int jj = 0; jj < 4; ++jj) {
                uint32_t o = b4_off + (uint32_t)(jj * 16 * PADK * 2);
                ldsm_x4(&bh[jj * 4], uBh + o);
                ldsm_x4(&bl[jj * 4], uBl + o);
            }
#pragma unroll
            for (int ni = 0; ni < 8; ++ni) {
                mma16816(acc[ni], ah, &bh[ni * 2]);
                mma16816(acc[ni], ah, &bl[ni * 2]);
                mma16816(acc[ni], al, &bh[ni * 2]);
            }
        }
    }

    const int gid = lane >> 2, tig = lane & 3;
#pragma unroll
    for (int half = 0; half < 2; ++half) {
        int r = wm + gid + half * 8;
        int m = m0 + r;
        if (m >= M) continue;
#pragma unroll
        for (int ni = 0; ni < 8; ++ni) {
            int col = wn + ni * 8 + tig * 2;
            float v0 = acc[ni][half * 2];
            float v1 = acc[ni][half * 2 + 1];
            if (bias) { v0 += bias[col]; v1 += bias[col + 1]; }
            if (relu) { v0 = fmaxf(v0, 0.f); v1 = fmaxf(v1, 0.f); }
            if (cef) {
                __half2 hv = __floats2half2_rn(v0, v1);
                *reinterpret_cast<__half2*>(cef + (size_t)m * DH + col) = hv;
            }
            if (chi) {
                uint32_t ph, pl;
                split2(v0, v1, ph, pl);
                *reinterpret_cast<uint32_t*>(chi + (size_t)m * DH + col) = ph;
                *reinterpret_cast<uint32_t*>(clo + (size_t)m * DH + col) = pl;
            }
        }
    }
}

// ---------------------------------------------------------------------------
// Merged head GEMM: A (h2 hi/lo) loaded once; 4 weight units; fp16 S out.
// ---------------------------------------------------------------------------
__global__ __launch_bounds__(512)
void k_gemm_head(const __nv_bfloat16* __restrict__ ah_, const __nv_bfloat16* __restrict__ al_,
                 const __nv_bfloat16* __restrict__ Wh4, const __nv_bfloat16* __restrict__ Wl4,
                 __half* __restrict__ S, int M)
{
    extern __shared__ __nv_bfloat16 sm[];
    __nv_bfloat16* sAh = sm;
    __nv_bfloat16* sAl = sAh + 128 * PADK;
    __nv_bfloat16* sBh = sAl + 128 * PADK;
    __nv_bfloat16* sBl = sBh + 128 * PADK;

    const int tid  = threadIdx.x;
    const int wid  = tid >> 5;
    const int lane = tid & 31;
    const int m0   = blockIdx.x * MTILE;
    const int wm   = (wid >> 1) * 16;
    const int wn   = (wid & 1) * 64;

    const uint32_t uAh = smem_to_u32(sAh);
    const uint32_t uAl = smem_to_u32(sAl);
    const uint32_t uBh = smem_to_u32(sBh);
    const uint32_t uBl = smem_to_u32(sBl);

#pragma unroll
    for (int it = 0; it < 4; ++it) {
        int idx = tid + it * 512;
        int row = idx >> 4;
        int c8  = (idx & 15) << 3;
        size_t soff = (size_t)row * PADK + c8;
        uint4 vh = make_uint4(0, 0, 0, 0), vl = vh;
        if (m0 + row < M) {
            vh = *reinterpret_cast<const uint4*>(ah_ + (size_t)(m0 + row) * DH + c8);
            vl = *reinterpret_cast<const uint4*>(al_ + (size_t)(m0 + row) * DH + c8);
        }
        *reinterpret_cast<uint4*>(sAh + soff) = vh;
        *reinterpret_cast<uint4*>(sAl + soff) = vl;
    }

    const int gid = lane >> 2, tig = lane & 3;

#pragma unroll 1
    for (int u = 0; u < 4; ++u) {
        const __nv_bfloat16* Wh = Wh4 + (size_t)u * 16384;
        const __nv_bfloat16* Wl = Wl4 + (size_t)u * 16384;

        __syncthreads();
#pragma unroll
        for (int it = 0; it < 4; ++it) {
            int idx = tid + it * 512;
            int row = idx >> 4;
            int c8  = (idx & 15) << 3;
            size_t soff = (size_t)row * PADK + c8;
            *reinterpret_cast<uint4*>(sBh + soff) =
                *reinterpret_cast<const uint4*>(Wh + (size_t)row * DH + c8);
            *reinterpret_cast<uint4*>(sBl + soff) =
                *reinterpret_cast<const uint4*>(Wl + (size_t)row * DH + c8);
        }
        __syncthreads();

        float acc[8][4];
#pragma unroll
        for (int ni = 0; ni < 8; ++ni)
#pragma unroll
            for (int q = 0; q < 4; ++q) acc[ni][q] = 0.f;

#pragma unroll 1
        for (int kc = 0; kc < 8; ++kc) {
            int k0 = kc * 16;
            uint32_t a_off = (uint32_t)(((wm + (lane & 15)) * PADK + k0 + (lane >> 4) * 8) * 2);
            uint32_t ah[4], al[4];
            ldsm_x4(ah, uAh + a_off);
            ldsm_x4(al, uAl + a_off);
            uint32_t b4_off = (uint32_t)(((wn + (lane & 7) + ((lane >> 4) << 3)) * PADK
                                          + k0 + ((lane >> 3) & 1) * 8) * 2);
            uint32_t bh[16], bl[16];
#pragma unroll
            for (int jj = 0; jj < 4; ++jj) {
                uint32_t o = b4_off + (uint32_t)(jj * 16 * PADK * 2);
                ldsm_x4(&bh[jj * 4], uBh + o);
                ldsm_x4(&bl[jj * 4], uBl + o);
            }
#pragma unroll
            for (int ni = 0; ni < 8; ++ni) {
                mma16816(acc[ni], ah, &bh[ni * 2]);
                mma16816(acc[ni], ah, &bl[ni * 2]);
                mma16816(acc[ni], al, &bh[ni * 2]);
            }
        }

#pragma unroll
        for (int half = 0; half < 2; ++half) {
            int r = wm + gid + half * 8;
            int m = m0 + r;
            if (m >= M) continue;
#pragma unroll
            for (int ni = 0; ni < 8; ++ni) {
                int col = wn + ni * 8 + tig * 2;
                __half2 hv = __floats2half2_rn(acc[ni][half * 2], acc[ni][half * 2 + 1]);
                *reinterpret_cast<__half2*>(S + (size_t)m * 512 + u * 128 + col) = hv;
            }
        }
    }
}

// ---------------------------------------------------------------------------
// Edge head, node-centric: warp per dst node; dst half loaded once,
// src half streamed per in-edge; scattered per-edge output.
// ---------------------------------------------------------------------------
__global__ __launch_bounds__(256)
void k_edge2(const int* __restrict__ csr, const int* __restrict__ csre,
             const int* __restrict__ off,
             const __half* __restrict__ S,
             const float* __restrict__ bm1, const float* __restrict__ Wm2,
             const float* __restrict__ bm2,
             const float* __restrict__ bv1, const float* __restrict__ Wv2,
             const float* __restrict__ bv2,
             float* __restrict__ outMean, float* __restrict__ outVar, int N)
{
    int g = blockIdx.x * blockDim.x + threadIdx.x;
    int n = g >> 5, lane = g & 31;
    if (n >= N) return;

    int p0 = off[n], p1 = off[n + 1];
    if (p0 == p1) return;

    float4 c_wm2 = *reinterpret_cast<const float4*>(&Wm2[lane * 4]);
    float4 c_wv2 = *reinterpret_cast<const float4*>(&Wv2[lane * 4]);
    float4 c_bm1 = *reinterpret_cast<const float4*>(&bm1[lane * 4]);
    float4 c_bv1 = *reinterpret_cast<const float4*>(&bv1[lane * 4]);
    float obm = bm2[0], obv = bv2[0];

    const __half* Dp = S + (size_t)n * 512;
    __half2 bmx[2], dvx[2];
    *reinterpret_cast<uint2*>(bmx) = *reinterpret_cast<const uint2*>(Dp + 256 + lane * 4);
    *reinterpret_cast<uint2*>(dvx) = *reinterpret_cast<const uint2*>(Dp + 384 + lane * 4);
    float2 b0 = __half22float2(bmx[0]), b1 = __half22float2(bmx[1]);
    float2 d0 = __half22float2(dvx[0]), d1 = __half22float2(dvx[1]);
    float tm0 = b0.x + c_bm1.x, tm1 = b0.y + c_bm1.y;
    float tm2 = b1.x + c_bm1.z, tm3 = b1.y + c_bm1.w;
    float tv0 = d0.x + c_bv1.x, tv1 = d0.y + c_bv1.y;
    float tv2 = d1.x + c_bv1.z, tv3 = d1.y + c_bv1.w;

#pragma unroll 1
    for (int p = p0; p < p1; ++p) {
        int s = csr[p];
        int e = csre[p];
        const __half* Sp = S + (size_t)s * 512;
        __half2 amx[2], cvx[2];
        *reinterpret_cast<uint2*>(amx) = *reinterpret_cast<const uint2*>(Sp + lane * 4);
        *reinterpret_cast<uint2*>(cvx) = *reinterpret_cast<const uint2*>(Sp + 128 + lane * 4);
        float2 a0 = __half22float2(amx[0]), a1 = __half22float2(amx[1]);
        float2 c0 = __half22float2(cvx[0]), c1 = __half22float2(cvx[1]);

        float pm = fmaxf(a0.x + tm0, 0.f) * c_wm2.x
                 + fmaxf(a0.y + tm1, 0.f) * c_wm2.y
                 + fmaxf(a1.x + tm2, 0.f) * c_wm2.z
                 + fmaxf(a1.y + tm3, 0.f) * c_wm2.w;
        float pv = fmaxf(c0.x + tv0, 0.f) * c_wv2.x
                 + fmaxf(c0.y + tv1, 0.f) * c_wv2.y
                 + fmaxf(c1.x + tv2, 0.f) * c_wv2.z
                 + fmaxf(c1.y + tv3, 0.f) * c_wv2.w;

#pragma unroll
        for (int o = 16; o > 0; o >>= 1) {
            pm += __shfl_xor_sync(0xFFFFFFFFu, pm, o);
            pv += __shfl_xor_sync(0xFFFFFFFFu, pv, o);
        }
        if (lane == 0) {
            outMean[e] = pm + obm;
            outVar[e]  = expf(0.5f * (pv + obv));
        }
    }
}

// ---------------------------------------------------------------------------
// kernel_launch
// ---------------------------------------------------------------------------
extern "C" void kernel_launch(void* const* d_in, const int* in_sizes, int n_in,
                              void* d_out, int out_size)
{
    const float* x       = (const float*)d_in[0];
    const int*   ei      = (const int*)d_in[1];
    const float* W1_rel  = (const float*)d_in[2];
    const float* b1      = (const float*)d_in[3];
    const float* W1_root = (const float*)d_in[4];
    const float* W2_rel  = (const float*)d_in[5];
    const float* b2      = (const float*)d_in[6];
    const float* W2_root = (const float*)d_in[7];
    const float* Wm1     = (const float*)d_in[8];
    const float* bm1     = (const float*)d_in[9];
    const float* Wm2     = (const float*)d_in[10];
    const float* bm2     = (const float*)d_in[11];
    const float* Wv1     = (const float*)d_in[12];
    const float* bv1     = (const float*)d_in[13];
    const float* Wv2     = (const float*)d_in[14];
    const float* bv2     = (const float*)d_in[15];

    int N = in_sizes[0] / DH;     // 50000
    int E = in_sizes[1] / 2;      // 800000
    float* out   = (float*)d_out;
    int    Ehalf = out_size / 2;

    float *agg;
    __half *S, *xf, *h1f;
    __nv_bfloat16 *h1h, *h1l, *h2h, *h2l, *Wh, *Wl;
    int *deg, *off, *cursor, *csr, *csre, *blk;
    cudaGetSymbolAddress((void**)&agg,    g_agg);
    cudaGetSymbolAddress((void**)&S,      g_S);
    cudaGetSymbolAddress((void**)&xf,     g_xf);
    cudaGetSymbolAddress((void**)&h1f,    g_h1f);
    cudaGetSymbolAddress((void**)&h1h,    g_h1h);
    cudaGetSymbolAddress((void**)&h1l,    g_h1l);
    cudaGetSymbolAddress((void**)&h2h,    g_h2h);
    cudaGetSymbolAddress((void**)&h2l,    g_h2l);
    cudaGetSymbolAddress((void**)&Wh,     g_Wh);
    cudaGetSymbolAddress((void**)&Wl,     g_Wl);
    cudaGetSymbolAddress((void**)&deg,    g_deg);
    cudaGetSymbolAddress((void**)&off,    g_off);
    cudaGetSymbolAddress((void**)&cursor, g_cursor);
    cudaGetSymbolAddress((void**)&csr,    g_csr);
    cudaGetSymbolAddress((void**)&csre,   g_csre);
    cudaGetSymbolAddress((void**)&blk,    g_blk);

    const int DYN_SMEM = 4 * 128 * PADK * 2;   // 139264 B
    static int smem_set = 0;
    if (!smem_set) {
        cudaFuncSetAttribute(k_gemm_mma,  cudaFuncAttributeMaxDynamicSharedMemorySize, DYN_SMEM);
        cudaFuncSetAttribute(k_gemm_head, cudaFuncAttributeMaxDynamicSharedMemorySize, DYN_SMEM);
        smem_set = 1;
    }

    int gemmB   = (N + MTILE - 1) / MTILE;
    int gatherB = (N * 32 + 255) / 256;
    int eB      = (E + 255) / 256;
    int scanB   = (N + 1023) / 1024;
    int n4      = N * (DH / 4);
    int halfB   = (n4 + 255) / 256;

    // Weight prep + x fp16 copy
    WSrc ws;
    ws.p[0] = W1_rel;  ws.p[1] = W1_root;
    ws.p[2] = W2_rel;  ws.p[3] = W2_root;
    ws.p[4] = Wm1;     ws.p[5] = Wv1;
    ws.p[6] = Wm1 + 128 * DH;  ws.p[7] = Wv1 + 128 * DH;
    k_wprep<<<dim3(64, 8), 256>>>(ws, Wh, Wl);
    k_half<<<halfB, 256>>>(x, xf, n4);

    // CSR build
    k_zeroi<<<(N + 256) / 256, 256>>>(deg, N + 1);
    k_hist<<<eB, 256>>>(ei, E, deg);
    k_scan1<<<scanB, 1024>>>(deg, off, blk, N);
    k_scan2<<<1, 64>>>(blk, off, scanB, N);
    k_scan3<<<scanB, 1024>>>(off, cursor, blk, N);
    k_fill<<<eB, 256>>>(ei, E, cursor, csr, csre);

    // Layer 1: agg(x_fp16)@W1rel + x@W1root  -> h1 (fp16 for gather, bf16 pair for GEMM2)
    k_gather<<<gatherB, 256>>>(xf, csr, off, agg, N);
    k_gemm_mma<<<gemmB, 512, DYN_SMEM>>>(
        agg, nullptr, nullptr, Wh + 0 * 16384, Wl + 0 * 16384,
        x,   nullptr, nullptr, Wh + 1 * 16384, Wl + 1 * 16384,
        b1, h1f, h1h, h1l, N, 1);

    // Layer 2: agg(h1_fp16)@W2rel + h1@W2root -> h2 (bf16 pair only)
    k_gather<<<gatherB, 256>>>(h1f, csr, off, agg, N);
    k_gemm_mma<<<gemmB, 512, DYN_SMEM>>>(
        agg,     nullptr, nullptr, Wh + 2 * 16384, Wl + 2 * 16384,
        nullptr, h1h,     h1l,     Wh + 3 * 16384, Wl + 3 * 16384,
        b2, nullptr, h2h, h2l, N, 1);

    // Head node tables
    k_gemm_head<<<gemmB, 512, DYN_SMEM>>>(h2h, h2l,
                                          Wh + 4 * 16384, Wl + 4 * 16384, S, N);

    // Edge heads (node-centric)
    k_edge2<<<gatherB, 256>>>(csr, csre, off, S, bm1, Wm2, bm2, bv1, Wv2, bv2,
                              out, out + Ehalf, N);
}

// round 17
// speedup vs baseline: 1.2309x; 1.2309x over previous
#include <cuda_runtime.h>
#include <cuda_fp16.h>
#include <math.h>
#include <stdint.h>

#define NMAX 50000
#define EMAX 800000
#define DH   128
#define MTILE 128
#define PADK 136      // fp16 elements per padded SMEM row (272 B)

// ---------------------------------------------------------------------------
// Scratch (__device__ globals; allocation-free rule)
// ---------------------------------------------------------------------------
__device__ float  g_agg[(size_t)NMAX * DH];
__device__ __half g_S  [(size_t)NMAX * 512];   // fp16 [Am|Cv|Bm|Dv] per node
__device__ __half g_xf [(size_t)NMAX * DH];    // fp16 x
__device__ __half g_h1f[(size_t)NMAX * DH];    // fp16 h1
__device__ __half g_h2f[(size_t)NMAX * DH];    // fp16 h2
__device__ __half g_Wh[8 * 128 * 128];         // fp16 weight hi, transposed [n][k]
__device__ __half g_Wl[8 * 128 * 128];         // fp16 weight lo (residual)

// CSR scratch
__device__ int g_deg   [NMAX + 64];
__device__ int g_off   [NMAX + 64];
__device__ int g_cursor[NMAX + 64];
__device__ int g_csr   [EMAX];
__device__ int g_csre  [EMAX];
__device__ int g_blk   [128];

// ---------------------------------------------------------------------------
// helpers
// ---------------------------------------------------------------------------
__device__ __forceinline__ uint32_t smem_to_u32(const void* p) {
    uint32_t a;
    asm("{ .reg .u64 t; cvta.to.shared.u64 t, %1; cvt.u32.u64 %0, t; }"
        : "=r"(a) : "l"(p));
    return a;
}
__device__ __forceinline__ void ldsm_x4(uint32_t* r, uint32_t addr) {
    asm volatile("ldmatrix.sync.aligned.m8n8.x4.shared.b16 {%0,%1,%2,%3}, [%4];"
                 : "=r"(r[0]), "=r"(r[1]), "=r"(r[2]), "=r"(r[3]) : "r"(addr));
}
__device__ __forceinline__ void mma16816f(float* c, const uint32_t* a, const uint32_t* b) {
    asm volatile(
        "mma.sync.aligned.m16n8k16.row.col.f32.f16.f16.f32 "
        "{%0,%1,%2,%3}, {%4,%5,%6,%7}, {%8,%9}, {%0,%1,%2,%3};"
        : "+f"(c[0]), "+f"(c[1]), "+f"(c[2]), "+f"(c[3])
        : "r"(a[0]), "r"(a[1]), "r"(a[2]), "r"(a[3]), "r"(b[0]), "r"(b[1]));
}

// ---------------------------------------------------------------------------
// fp32 -> fp16 convert (vectorized x4)
// ---------------------------------------------------------------------------
__global__ void k_half(const float* __restrict__ src, __half* __restrict__ dst, int n4)
{
    int i = blockIdx.x * blockDim.x + threadIdx.x;
    if (i >= n4) return;
    float4 v = reinterpret_cast<const float4*>(src)[i];
    __half2 p0 = __floats2half2_rn(v.x, v.y);
    __half2 p1 = __floats2half2_rn(v.z, v.w);
    reinterpret_cast<__half2*>(dst)[i * 2]     = p0;
    reinterpret_cast<__half2*>(dst)[i * 2 + 1] = p1;
}

// ---------------------------------------------------------------------------
// CSR build
// ---------------------------------------------------------------------------
__global__ void k_zeroi(int* __restrict__ p, int n)
{
    int i = blockIdx.x * blockDim.x + threadIdx.x;
    if (i < n) p[i] = 0;
}

__global__ void k_hist(const int* __restrict__ ei, int E, int* __restrict__ deg)
{
    int e = blockIdx.x * blockDim.x + threadIdx.x;
    if (e < E) atomicAdd(&deg[ei[(size_t)E + e]], 1);
}

__global__ void k_scan1(const int* __restrict__ deg, int* __restrict__ off,
                        int* __restrict__ blk, int N)
{
    __shared__ int sWarp[32];
    const int t    = threadIdx.x;
    const int lane = t & 31;
    const int w    = t >> 5;
    int i = blockIdx.x * 1024 + t;
    int v = (i < N) ? deg[i] : 0;

    int x = v;
#pragma unroll
    for (int d = 1; d < 32; d <<= 1) {
        int y = __shfl_up_sync(0xFFFFFFFFu, x, d);
        if (lane >= d) x += y;
    }
    if (lane == 31) sWarp[w] = x;
    __syncthreads();
    if (w == 0) {
        int s = sWarp[lane];
#pragma unroll
        for (int d = 1; d < 32; d <<= 1) {
            int y = __shfl_up_sync(0xFFFFFFFFu, s, d);
            if (lane >= d) s += y;
        }
        sWarp[lane] = s;
    }
    __syncthreads();
    int warpBase = (w > 0) ? sWarp[w - 1] : 0;
    if (i < N) off[i] = warpBase + (x - v);
    if (t == 1023) blk[blockIdx.x] = sWarp[31];
}

__global__ void k_scan2(int* __restrict__ blk, int* __restrict__ off, int nB, int N)
{
    const int t = threadIdx.x;   // 64 threads
    int v = (t < nB) ? blk[t] : 0;
    int x = v;
#pragma unroll
    for (int d = 1; d < 32; d <<= 1) {
        int y = __shfl_up_sync(0xFFFFFFFFu, x, d);
        if ((t & 31) >= d) x += y;
    }
    __shared__ int sw[2];
    if ((t & 31) == 31) sw[t >> 5] = x;
    __syncthreads();
    int base = (t >= 32) ? sw[0] : 0;
    int excl = base + x - v;
    if (t < nB) blk[t] = excl;
    if (t == 63) off[N] = base + ((nB > 32) ? sw[1] : ((nB > 0) ? sw[0] : 0));
}

__global__ void k_scan3(int* __restrict__ off, int* __restrict__ cursor,
                        const int* __restrict__ blk, int N)
{
    int i = blockIdx.x * 1024 + threadIdx.x;
    if (i < N) {
        int o = off[i] + blk[blockIdx.x];
        off[i] = o;
        cursor[i] = o;
    }
}

__global__ void k_fill(const int* __restrict__ ei, int E,
                       int* __restrict__ cursor,
                       int* __restrict__ csr, int* __restrict__ csre)
{
    int e = blockIdx.x * blockDim.x + threadIdx.x;
    if (e >= E) return;
    int s = ei[e];
    int d = ei[(size_t)E + e];
    int pos = atomicAdd(&cursor[d], 1);
    csr[pos]  = s;
    csre[pos] = e;
}

// ---------------------------------------------------------------------------
// gather-reduce (fp16 input): agg[n] = sum_{e: dst=n} feat[src_e]; warp/node
// ---------------------------------------------------------------------------
__global__ void k_gather(const __half* __restrict__ feat,
                         const int* __restrict__ csr, const int* __restrict__ off,
                         float* __restrict__ agg, int N)
{
    int g = blockIdx.x * blockDim.x + threadIdx.x;
    int n = g >> 5, lane = g & 31;
    if (n >= N) return;
    int s0 = off[n], s1 = off[n + 1];
    float4 acc = make_float4(0.f, 0.f, 0.f, 0.f);
    for (int base = s0; base < s1; base += 32) {
        int cnt = min(32, s1 - base);
        int idx = (base + lane < s1) ? csr[base + lane] : 0;
#pragma unroll 4
        for (int j = 0; j < cnt; ++j) {
            int s = __shfl_sync(0xFFFFFFFFu, idx, j);
            uint2 raw = *reinterpret_cast<const uint2*>(&feat[(size_t)s * DH + lane * 4]);
            __half2 h0 = *reinterpret_cast<__half2*>(&raw.x);
            __half2 h1 = *reinterpret_cast<__half2*>(&raw.y);
            float2 f0 = __half22float2(h0);
            float2 f1 = __half22float2(h1);
            acc.x += f0.x; acc.y += f0.y; acc.z += f1.x; acc.w += f1.y;
        }
    }
    *reinterpret_cast<float4*>(&agg[(size_t)n * DH + lane * 4]) = acc;
}

// ---------------------------------------------------------------------------
// weight prep: transpose [k][n] -> [n][k], split to fp16 hi/lo. 8 units.
// ---------------------------------------------------------------------------
struct WSrc { const float* p[8]; };

__global__ void k_wprep(WSrc w,
                        __half* __restrict__ oh,
                        __half* __restrict__ ol)
{
    int u = blockIdx.y;
    int i = blockIdx.x * 256 + threadIdx.x;
    int n = i >> 7, k = i & 127;
    float v = w.p[u][(size_t)k * DH + n];
    __half h = __float2half_rn(v);
    oh[(size_t)u * 16384 + i] = h;
    ol[(size_t)u * 16384 + i] = __float2half_rn(v - __half2float(h));
}

// ---------------------------------------------------------------------------
// mma.sync fp16 GEMM, 2-term W-compensated split (A @ Wh + A @ Wl).
// 256 threads, 8 warps, warp tile 32x64, 3 SMEM tiles (A, Wh, Wl) -> occ 2.
// A per phase: fp32 (converted in fill) or fp16. Output fp16 (cef).
// ---------------------------------------------------------------------------
__global__ __launch_bounds__(256, 2)
void k_gemm_mma(const float* __restrict__ a0f, const __half* __restrict__ a0h,
                const __half* __restrict__ w0h, const __half* __restrict__ w0l,
                const float* __restrict__ a1f, const __half* __restrict__ a1h,
                const __half* __restrict__ w1h, const __half* __restrict__ w1l,
                const float* __restrict__ bias,
                __half* __restrict__ cef,
                int M, int relu)
{
    extern __shared__ __half sm[];
    __half* sA  = sm;
    __half* sBh = sA  + 128 * PADK;
    __half* sBl = sBh + 128 * PADK;

    const int tid  = threadIdx.x;
    const int wid  = tid >> 5;
    const int lane = tid & 31;
    const int m0   = blockIdx.x * MTILE;
    const int wm   = (wid >> 1) * 32;
    const int wn   = (wid & 1) * 64;

    const uint32_t uA  = smem_to_u32(sA);
    const uint32_t uBh = smem_to_u32(sBh);
    const uint32_t uBl = smem_to_u32(sBl);

    float acc[2][8][4];
#pragma unroll
    for (int mi = 0; mi < 2; ++mi)
#pragma unroll
        for (int ni = 0; ni < 8; ++ni)
#pragma unroll
            for (int q = 0; q < 4; ++q) acc[mi][ni][q] = 0.f;

#pragma unroll 1
    for (int phase = 0; phase < 2; ++phase) {
        const float*  Af = phase ? a1f : a0f;
        const __half* Ah = phase ? a1h : a0h;
        const __half* Wh = phase ? w1h : w0h;
        const __half* Wl = phase ? w1l : w0l;
        if (Af == nullptr && Ah == nullptr) break;

        __syncthreads();
        // A tile: 2048 uint4 slots (128 rows x 16 slots), 8 iters
#pragma unroll
        for (int it = 0; it < 8; ++it) {
            int idx = tid + it * 256;
            int row = idx >> 4;
            int c8  = (idx & 15) << 3;
            size_t soff = (size_t)row * PADK + c8;
            uint4 v = make_uint4(0, 0, 0, 0);
            if (m0 + row < M) {
                if (Af) {
                    const float* ap = Af + (size_t)(m0 + row) * DH + c8;
                    float4 f0 = *reinterpret_cast<const float4*>(ap);
                    float4 f1 = *reinterpret_cast<const float4*>(ap + 4);
                    __half2 p0 = __floats2half2_rn(f0.x, f0.y);
                    __half2 p1 = __floats2half2_rn(f0.z, f0.w);
                    __half2 p2 = __floats2half2_rn(f1.x, f1.y);
                    __half2 p3 = __floats2half2_rn(f1.z, f1.w);
                    v.x = *reinterpret_cast<uint32_t*>(&p0);
                    v.y = *reinterpret_cast<uint32_t*>(&p1);
                    v.z = *reinterpret_cast<uint32_t*>(&p2);
                    v.w = *reinterpret_cast<uint32_t*>(&p3);
                } else {
                    v = *reinterpret_cast<const uint4*>(Ah + (size_t)(m0 + row) * DH + c8);
                }
            }
            *reinterpret_cast<uint4*>(sA + soff) = v;
        }
        // W tiles: 2x2048 slots, 16 iters
#pragma unroll
        for (int it = 0; it < 8; ++it) {
            int idx = tid + it * 256;
            int row = idx >> 4;
            int c8  = (idx & 15) << 3;
            size_t soff = (size_t)row * PADK + c8;
            *reinterpret_cast<uint4*>(sBh + soff) =
                *reinterpret_cast<const uint4*>(Wh + (size_t)row * DH + c8);
            *reinterpret_cast<uint4*>(sBl + soff) =
                *reinterpret_cast<const uint4*>(Wl + (size_t)row * DH + c8);
        }
        __syncthreads();

#pragma unroll 1
        for (int kc = 0; kc < 8; ++kc) {
            int k0 = kc * 16;
            uint32_t a_off = (uint32_t)(((wm + (lane & 15)) * PADK + k0 + (lane >> 4) * 8) * 2);
            uint32_t ah[2][4];
            ldsm_x4(ah[0], uA + a_off);
            ldsm_x4(ah[1], uA + a_off + (uint32_t)(16 * PADK * 2));
            uint32_t b4_off = (uint32_t)(((wn + (lane & 7) + ((lane >> 4) << 3)) * PADK
                                          + k0 + ((lane >> 3) & 1) * 8) * 2);
            uint32_t bh[16], bl[16];
#pragma unroll
            for (int jj = 0; jj < 4; ++jj) {
                uint32_t o = b4_off + (uint32_t)(jj * 16 * PADK * 2);
                ldsm_x4(&bh[jj * 4], uBh + o);
                ldsm_x4(&bl[jj * 4], uBl + o);
            }
#pragma unroll
            for (int mi = 0; mi < 2; ++mi)
#pragma unroll
                for (int ni = 0; ni < 8; ++ni) {
                    mma16816f(acc[mi][ni], ah[mi], &bh[ni * 2]);
                    mma16816f(acc[mi][ni], ah[mi], &bl[ni * 2]);
                }
        }
    }

    const int gid = lane >> 2, tig = lane & 3;
#pragma unroll
    for (int mi = 0; mi < 2; ++mi) {
#pragma unroll
        for (int half = 0; half < 2; ++half) {
            int r = wm + mi * 16 + gid + half * 8;
            int m = m0 + r;
            if (m >= M) continue;
#pragma unroll
            for (int ni = 0; ni < 8; ++ni) {
                int col = wn + ni * 8 + tig * 2;
                float v0 = acc[mi][ni][half * 2];
                float v1 = acc[mi][ni][half * 2 + 1];
                if (bias) { v0 += bias[col]; v1 += bias[col + 1]; }
                if (relu) { v0 = fmaxf(v0, 0.f); v1 = fmaxf(v1, 0.f); }
                __half2 hv = __floats2half2_rn(v0, v1);
                *reinterpret_cast<__half2*>(cef + (size_t)m * DH + col) = hv;
            }
        }
    }
}

// ---------------------------------------------------------------------------
// Merged head GEMM: A (h2 fp16) loaded once; 4 weight units; fp16 S out.
// 256 threads, 8 warps, warp tile 32x64, 3 SMEM tiles -> occ 2.
// ---------------------------------------------------------------------------
__global__ __launch_bounds__(256, 2)
void k_gemm_head(const __half* __restrict__ a_, 
                 const __half* __restrict__ Wh4, const __half* __restrict__ Wl4,
                 __half* __restrict__ S, int M)
{
    extern __shared__ __half sm[];
    __half* sA  = sm;
    __half* sBh = sA  + 128 * PADK;
    __half* sBl = sBh + 128 * PADK;

    const int tid  = threadIdx.x;
    const int wid  = tid >> 5;
    const int lane = tid & 31;
    const int m0   = blockIdx.x * MTILE;
    const int wm   = (wid >> 1) * 32;
    const int wn   = (wid & 1) * 64;

    const uint32_t uA  = smem_to_u32(sA);
    const uint32_t uBh = smem_to_u32(sBh);
    const uint32_t uBl = smem_to_u32(sBl);

#pragma unroll
    for (int it = 0; it < 8; ++it) {
        int idx = tid + it * 256;
        int row = idx >> 4;
        int c8  = (idx & 15) << 3;
        size_t soff = (size_t)row * PADK + c8;
        uint4 v = make_uint4(0, 0, 0, 0);
        if (m0 + row < M)
            v = *reinterpret_cast<const uint4*>(a_ + (size_t)(m0 + row) * DH + c8);
        *reinterpret_cast<uint4*>(sA + soff) = v;
    }

    const int gid = lane >> 2, tig = lane & 3;

#pragma unroll 1
    for (int u = 0; u < 4; ++u) {
        const __half* Wh = Wh4 + (size_t)u * 16384;
        const __half* Wl = Wl4 + (size_t)u * 16384;

        __syncthreads();
#pragma unroll
        for (int it = 0; it < 8; ++it) {
            int idx = tid + it * 256;
            int row = idx >> 4;
            int c8  = (idx & 15) << 3;
            size_t soff = (size_t)row * PADK + c8;
            *reinterpret_cast<uint4*>(sBh + soff) =
                *reinterpret_cast<const uint4*>(Wh + (size_t)row * DH + c8);
            *reinterpret_cast<uint4*>(sBl + soff) =
                *reinterpret_cast<const uint4*>(Wl + (size_t)row * DH + c8);
        }
        __syncthreads();

        float acc[2][8][4];
#pragma unroll
        for (int mi = 0; mi < 2; ++mi)
#pragma unroll
            for (int ni = 0; ni < 8; ++ni)
#pragma unroll
                for (int q = 0; q < 4; ++q) acc[mi][ni][q] = 0.f;

#pragma unroll 1
        for (int kc = 0; kc < 8; ++kc) {
            int k0 = kc * 16;
            uint32_t a_off = (uint32_t)(((wm + (lane & 15)) * PADK + k0 + (lane >> 4) * 8) * 2);
            uint32_t ah[2][4];
            ldsm_x4(ah[0], uA + a_off);
            ldsm_x4(ah[1], uA + a_off + (uint32_t)(16 * PADK * 2));
            uint32_t b4_off = (uint32_t)(((wn + (lane & 7) + ((lane >> 4) << 3)) * PADK
                                          + k0 + ((lane >> 3) & 1) * 8) * 2);
            uint32_t bh[16], bl[16];
#pragma unroll
            for (int jj = 0; jj < 4; ++jj) {
                uint32_t o = b4_off + (uint32_t)(jj * 16 * PADK * 2);
                ldsm_x4(&bh[jj * 4], uBh + o);
                ldsm_x4(&bl[jj * 4], uBl + o);
            }
#pragma unroll
            for (int mi = 0; mi < 2; ++mi)
#pragma unroll
                for (int ni = 0; ni < 8; ++ni) {
                    mma16816f(acc[mi][ni], ah[mi], &bh[ni * 2]);
                    mma16816f(acc[mi][ni], ah[mi], &bl[ni * 2]);
                }
        }

#pragma unroll
        for (int mi = 0; mi < 2; ++mi) {
#pragma unroll
            for (int half = 0; half < 2; ++half) {
                int r = wm + mi * 16 + gid + half * 8;
                int m = m0 + r;
                if (m >= M) continue;
#pragma unroll
                for (int ni = 0; ni < 8; ++ni) {
                    int col = wn + ni * 8 + tig * 2;
                    __half2 hv = __floats2half2_rn(acc[mi][ni][half * 2],
                                                   acc[mi][ni][half * 2 + 1]);
                    *reinterpret_cast<__half2*>(S + (size_t)m * 512 + u * 128 + col) = hv;
                }
            }
        }
    }
}

// ---------------------------------------------------------------------------
// Edge head, node-centric: warp per dst node.
// ---------------------------------------------------------------------------
__global__ __launch_bounds__(256)
void k_edge2(const int* __restrict__ csr, const int* __restrict__ csre,
             const int* __restrict__ off,
             const __half* __restrict__ S,
             const float* __restrict__ bm1, const float* __restrict__ Wm2,
             const float* __restrict__ bm2,
             const float* __restrict__ bv1, const float* __restrict__ Wv2,
             const float* __restrict__ bv2,
             float* __restrict__ outMean, float* __restrict__ outVar, int N)
{
    int g = blockIdx.x * blockDim.x + threadIdx.x;
    int n = g >> 5, lane = g & 31;
    if (n >= N) return;

    int p0 = off[n], p1 = off[n + 1];
    if (p0 == p1) return;

    float4 c_wm2 = *reinterpret_cast<const float4*>(&Wm2[lane * 4]);
    float4 c_wv2 = *reinterpret_cast<const float4*>(&Wv2[lane * 4]);
    float4 c_bm1 = *reinterpret_cast<const float4*>(&bm1[lane * 4]);
    float4 c_bv1 = *reinterpret_cast<const float4*>(&bv1[lane * 4]);
    float obm = bm2[0], obv = bv2[0];

    const __half* Dp = S + (size_t)n * 512;
    __half2 bmx[2], dvx[2];
    *reinterpret_cast<uint2*>(bmx) = *reinterpret_cast<const uint2*>(Dp + 256 + lane * 4);
    *reinterpret_cast<uint2*>(dvx) = *reinterpret_cast<const uint2*>(Dp + 384 + lane * 4);
    float2 b0 = __half22float2(bmx[0]), b1 = __half22float2(bmx[1]);
    float2 d0 = __half22float2(dvx[0]), d1 = __half22float2(dvx[1]);
    float tm0 = b0.x + c_bm1.x, tm1 = b0.y + c_bm1.y;
    float tm2 = b1.x + c_bm1.z, tm3 = b1.y + c_bm1.w;
    float tv0 = d0.x + c_bv1.x, tv1 = d0.y + c_bv1.y;
    float tv2 = d1.x + c_bv1.z, tv3 = d1.y + c_bv1.w;

#pragma unroll 1
    for (int p = p0; p < p1; ++p) {
        int s = csr[p];
        int e = csre[p];
        const __half* Sp = S + (size_t)s * 512;
        __half2 amx[2], cvx[2];
        *reinterpret_cast<uint2*>(amx) = *reinterpret_cast<const uint2*>(Sp + lane * 4);
        *reinterpret_cast<uint2*>(cvx) = *reinterpret_cast<const uint2*>(Sp + 128 + lane * 4);
        float2 a0 = __half22float2(amx[0]), a1 = __half22float2(amx[1]);
        float2 c0 = __half22float2(cvx[0]), c1 = __half22float2(cvx[1]);

        float pm = fmaxf(a0.x + tm0, 0.f) * c_wm2.x
                 + fmaxf(a0.y + tm1, 0.f) * c_wm2.y
                 + fmaxf(a1.x + tm2, 0.f) * c_wm2.z
                 + fmaxf(a1.y + tm3, 0.f) * c_wm2.w;
        float pv = fmaxf(c0.x + tv0, 0.f) * c_wv2.x
                 + fmaxf(c0.y + tv1, 0.f) * c_wv2.y
                 + fmaxf(c1.x + tv2, 0.f) * c_wv2.z
                 + fmaxf(c1.y + tv3, 0.f) * c_wv2.w;

#pragma unroll
        for (int o = 16; o > 0; o >>= 1) {
            pm += __shfl_xor_sync(0xFFFFFFFFu, pm, o);
            pv += __shfl_xor_sync(0xFFFFFFFFu, pv, o);
        }
        if (lane == 0) {
            outMean[e] = pm + obm;
            outVar[e]  = expf(0.5f * (pv + obv));
        }
    }
}

// ---------------------------------------------------------------------------
// kernel_launch
// ---------------------------------------------------------------------------
extern "C" void kernel_launch(void* const* d_in, const int* in_sizes, int n_in,
                              void* d_out, int out_size)
{
    const float* x       = (const float*)d_in[0];
    const int*   ei      = (const int*)d_in[1];
    const float* W1_rel  = (const float*)d_in[2];
    const float* b1      = (const float*)d_in[3];
    const float* W1_root = (const float*)d_in[4];
    const float* W2_rel  = (const float*)d_in[5];
    const float* b2      = (const float*)d_in[6];
    const float* W2_root = (const float*)d_in[7];
    const float* Wm1     = (const float*)d_in[8];
    const float* bm1     = (const float*)d_in[9];
    const float* Wm2     = (const float*)d_in[10];
    const float* bm2     = (const float*)d_in[11];
    const float* Wv1     = (const float*)d_in[12];
    const float* bv1     = (const float*)d_in[13];
    const float* Wv2     = (const float*)d_in[14];
    const float* bv2     = (const float*)d_in[15];

    int N = in_sizes[0] / DH;     // 50000
    int E = in_sizes[1] / 2;      // 800000
    float* out   = (float*)d_out;
    int    Ehalf = out_size / 2;

    float *agg;
    __half *S, *xf, *h1f, *h2f, *Wh, *Wl;
    int *deg, *off, *cursor, *csr, *csre, *blk;
    cudaGetSymbolAddress((void**)&agg,    g_agg);
    cudaGetSymbolAddress((void**)&S,      g_S);
    cudaGetSymbolAddress((void**)&xf,     g_xf);
    cudaGetSymbolAddress((void**)&h1f,    g_h1f);
    cudaGetSymbolAddress((void**)&h2f,    g_h2f);
    cudaGetSymbolAddress((void**)&Wh,     g_Wh);
    cudaGetSymbolAddress((void**)&Wl,     g_Wl);
    cudaGetSymbolAddress((void**)&deg,    g_deg);
    cudaGetSymbolAddress((void**)&off,    g_off);
    cudaGetSymbolAddress((void**)&cursor, g_cursor);
    cudaGetSymbolAddress((void**)&csr,    g_csr);
    cudaGetSymbolAddress((void**)&csre,   g_csre);
    cudaGetSymbolAddress((void**)&blk,    g_blk);

    const int DYN_SMEM = 3 * 128 * PADK * 2;   // 104448 B -> 2 CTAs/SM
    static int smem_set = 0;
    if (!smem_set) {
        cudaFuncSetAttribute(k_gemm_mma,  cudaFuncAttributeMaxDynamicSharedMemorySize, DYN_SMEM);
        cudaFuncSetAttribute(k_gemm_head, cudaFuncAttributeMaxDynamicSharedMemorySize, DYN_SMEM);
        smem_set = 1;
    }

    int gemmB   = (N + MTILE - 1) / MTILE;
    int gatherB = (N * 32 + 255) / 256;
    int eB      = (E + 255) / 256;
    int scanB   = (N + 1023) / 1024;
    int n4      = N * (DH / 4);
    int halfB   = (n4 + 255) / 256;

    // Weight prep + x fp16 copy
    WSrc ws;
    ws.p[0] = W1_rel;  ws.p[1] = W1_root;
    ws.p[2] = W2_rel;  ws.p[3] = W2_root;
    ws.p[4] = Wm1;     ws.p[5] = Wv1;
    ws.p[6] = Wm1 + 128 * DH;  ws.p[7] = Wv1 + 128 * DH;
    k_wprep<<<dim3(64, 8), 256>>>(ws, Wh, Wl);
    k_half<<<halfB, 256>>>(x, xf, n4);

    // CSR build
    k_zeroi<<<(N + 256) / 256, 256>>>(deg, N + 1);
    k_hist<<<eB, 256>>>(ei, E, deg);
    k_scan1<<<scanB, 1024>>>(deg, off, blk, N);
    k_scan2<<<1, 64>>>(blk, off, scanB, N);
    k_scan3<<<scanB, 1024>>>(off, cursor, blk, N);
    k_fill<<<eB, 256>>>(ei, E, cursor, csr, csre);

    // Layer 1: agg(x)@W1rel + x@W1root -> h1f
    k_gather<<<gatherB, 256>>>(xf, csr, off, agg, N);
    k_gemm_mma<<<gemmB, 256, DYN_SMEM>>>(
        agg, nullptr, Wh + 0 * 16384, Wl + 0 * 16384,
        nullptr, xf,  Wh + 1 * 16384, Wl + 1 * 16384,
        b1, h1f, N, 1);

    // Layer 2: agg(h1)@W2rel + h1@W2root -> h2f
    k_gather<<<gatherB, 256>>>(h1f, csr, off, agg, N);
    k_gemm_mma<<<gemmB, 256, DYN_SMEM>>>(
        agg, nullptr,  Wh + 2 * 16384, Wl + 2 * 16384,
        nullptr, h1f,  Wh + 3 * 16384, Wl + 3 * 16384,
        b2, h2f, N, 1);

    // Head node tables
    k_gemm_head<<<gemmB, 256, DYN_SMEM>>>(h2f, Wh + 4 * 16384, Wl + 4 * 16384, S, N);

    // Edge heads (node-centric)
    k_edge2<<<gatherB, 256>>>(csr, csre, off, S, bm1, Wm2, bm2, bv1, Wv2, bv2,
                              out, out + Ehalf, N);
}